// round 1
// baseline (speedup 1.0000x reference)
#include <cuda_runtime.h>
#include <cuda_bf16.h>

// Problem constants
#define Bsz 2
#define E 2048
#define C 512
#define H 8
#define D 64
#define M_TOT (Bsz * E)       // 4096
#define CAP 320               // per-row nnz capacity (mean 102, sd ~10)

// ---------------- scratch (device globals; no allocation) ----------------
__device__ float g_q[M_TOT * C];
__device__ float g_k[M_TOT * C];
__device__ float g_v[M_TOT * C];
__device__ float g_o[M_TOT * C];
__device__ float g_p[M_TOT * C];
__device__ int   g_cnt[E];
__device__ int   g_cidx[E * CAP];
__device__ float g_cval[E * CAP];
__device__ float g_vsum[Bsz * H * D];

// ---------------- SGEMM: C[m,n] = sum_k A[m,k] * B[n,k]  (NT) -------------
// BM=BN=128, BK=8, 256 threads, 8x8 microtile. blockIdx.z selects B/C pair.
#define BM 128
#define BN 128
#define BK 8

__global__ __launch_bounds__(256) void sgemm_nt(
    const float* __restrict__ A,
    const float* __restrict__ B0, const float* __restrict__ B1, const float* __restrict__ B2,
    float* __restrict__ C0, float* __restrict__ C1, float* __restrict__ C2,
    int M, int N, int K)
{
    int z = blockIdx.z;
    const float* Bm = (z == 0) ? B0 : (z == 1 ? B1 : B2);
    float*       Cm = (z == 0) ? C0 : (z == 1 ? C1 : C2);

    __shared__ float As[BK][BM];
    __shared__ float Bs[BK][BN];

    int tid = threadIdx.x;
    int m0 = blockIdx.y * BM;
    int n0 = blockIdx.x * BN;

    int lr = tid >> 1;            // 0..127
    int lc = (tid & 1) * 4;       // 0 or 4

    const float* Ag = A  + (size_t)(m0 + lr) * K + lc;
    const float* Bg = Bm + (size_t)(n0 + lr) * K + lc;

    int ty = tid >> 4;            // 0..15
    int tx = tid & 15;            // 0..15

    float acc[8][8];
    #pragma unroll
    for (int i = 0; i < 8; i++)
        #pragma unroll
        for (int j = 0; j < 8; j++) acc[i][j] = 0.0f;

    for (int k0 = 0; k0 < K; k0 += BK) {
        float4 a = *reinterpret_cast<const float4*>(Ag + k0);
        float4 b = *reinterpret_cast<const float4*>(Bg + k0);
        __syncthreads();
        As[lc + 0][lr] = a.x; As[lc + 1][lr] = a.y;
        As[lc + 2][lr] = a.z; As[lc + 3][lr] = a.w;
        Bs[lc + 0][lr] = b.x; Bs[lc + 1][lr] = b.y;
        Bs[lc + 2][lr] = b.z; Bs[lc + 3][lr] = b.w;
        __syncthreads();

        #pragma unroll
        for (int kk = 0; kk < BK; kk++) {
            float af[8], bf[8];
            *reinterpret_cast<float4*>(af)     = *reinterpret_cast<const float4*>(&As[kk][ty * 8]);
            *reinterpret_cast<float4*>(af + 4) = *reinterpret_cast<const float4*>(&As[kk][ty * 8 + 4]);
            *reinterpret_cast<float4*>(bf)     = *reinterpret_cast<const float4*>(&Bs[kk][tx * 8]);
            *reinterpret_cast<float4*>(bf + 4) = *reinterpret_cast<const float4*>(&Bs[kk][tx * 8 + 4]);
            #pragma unroll
            for (int i = 0; i < 8; i++)
                #pragma unroll
                for (int j = 0; j < 8; j++)
                    acc[i][j] += af[i] * bf[j];
        }
    }

    #pragma unroll
    for (int i = 0; i < 8; i++) {
        float* crow = Cm + (size_t)(m0 + ty * 8 + i) * N + n0 + tx * 8;
        *reinterpret_cast<float4*>(crow)     = make_float4(acc[i][0], acc[i][1], acc[i][2], acc[i][3]);
        *reinterpret_cast<float4*>(crow + 4) = make_float4(acc[i][4], acc[i][5], acc[i][6], acc[i][7]);
    }
}

// ---------------- mask -> per-row compressed lists ------------------------
__global__ __launch_bounds__(128) void build_csr(const float* __restrict__ mask)
{
    int row  = blockIdx.x * 4 + (threadIdx.x >> 5);
    int lane = threadIdx.x & 31;
    if (row >= E) return;

    int cnt = 0;
    const float* mrow = mask + (size_t)row * E;
    for (int j0 = 0; j0 < E; j0 += 32) {
        float v = mrow[j0 + lane];
        unsigned bal = __ballot_sync(0xFFFFFFFFu, v != 0.0f);
        if (v != 0.0f) {
            int off = cnt + __popc(bal & ((1u << lane) - 1u));
            if (off < CAP) {
                g_cidx[row * CAP + off] = j0 + lane;
                g_cval[row * CAP + off] = v;
            }
        }
        cnt += __popc(bal);
    }
    if (lane == 0) g_cnt[row] = (cnt > CAP) ? CAP : cnt;
}

// ---------------- vsum[b,h,d] = sum_e v[b,e,h*64+d] -----------------------
__global__ __launch_bounds__(512) void vsum_kernel()
{
    int bh = blockIdx.x;           // 0..15
    int b = bh >> 3, h = bh & 7;
    int d  = threadIdx.x & 63;
    int sl = threadIdx.x >> 6;     // 0..7
    const float* vb = g_v + (size_t)b * E * C + h * D + d;
    float s = 0.0f;
    #pragma unroll 4
    for (int e = sl; e < E; e += 8) s += vb[(size_t)e * C];
    __shared__ float red[8][64];
    red[sl][d] = s;
    __syncthreads();
    if (sl == 0) {
        float t = 0.0f;
        #pragma unroll
        for (int i = 0; i < 8; i++) t += red[i][d];
        g_vsum[bh * D + d] = t;
    }
}

// ---------------- sparse masked attention: warp per (b,h,q) ----------------
__global__ __launch_bounds__(256) void attn_sparse()
{
    int g    = blockIdx.x * 8 + (threadIdx.x >> 5);   // 0..32767
    int lane = threadIdx.x & 31;
    int b = g >> 14;            // / (H*E)
    int h = (g >> 11) & 7;
    int q = g & (E - 1);

    const float* qr = g_q + ((size_t)(b * E + q)) * C + h * D;
    float qa = qr[lane];
    float qb = qr[lane + 32];

    float acc0 = 0.5f * g_vsum[(b * H + h) * D + lane];
    float acc1 = 0.5f * g_vsum[(b * H + h) * D + 32 + lane];

    int n = g_cnt[q];
    const int*   ci = g_cidx + q * CAP;
    const float* cv = g_cval + q * CAP;
    size_t base = (size_t)b * E * C + h * D;

    for (int i = 0; i < n; i++) {
        int   kidx = ci[i];
        float mval = cv[i];
        const float* kr = g_k + base + (size_t)kidx * C;
        const float* vr = g_v + base + (size_t)kidx * C;
        float p = qa * kr[lane] + qb * kr[lane + 32];
        p += __shfl_xor_sync(0xFFFFFFFFu, p, 16);
        p += __shfl_xor_sync(0xFFFFFFFFu, p, 8);
        p += __shfl_xor_sync(0xFFFFFFFFu, p, 4);
        p += __shfl_xor_sync(0xFFFFFFFFu, p, 2);
        p += __shfl_xor_sync(0xFFFFFFFFu, p, 1);
        float s = 0.5f * mval * p;
        acc0 += s * vr[lane];
        acc1 += s * vr[lane + 32];
    }

    float* orow = g_o + ((size_t)(b * E + q)) * C + h * D;
    orow[lane]      = acc0;
    orow[lane + 32] = acc1;
}

// ---------------- bias + LayerNorm + residual ------------------------------
__global__ __launch_bounds__(128) void ln_residual(
    const float* __restrict__ x,  const float* __restrict__ bp,
    const float* __restrict__ w,  const float* __restrict__ bb,
    const float* __restrict__ gamma, float* __restrict__ out)
{
    int row = blockIdx.x;          // 0..4095
    int tid = threadIdx.x;         // 128
    const float* pr = g_p + (size_t)row * C;

    float y[4];
    float sum = 0.0f, sq = 0.0f;
    #pragma unroll
    for (int i = 0; i < 4; i++) {
        int c = tid + i * 128;
        y[i] = pr[c] + bp[c];
        sum += y[i];
        sq  += y[i] * y[i];
    }
    #pragma unroll
    for (int o = 16; o; o >>= 1) {
        sum += __shfl_xor_sync(0xFFFFFFFFu, sum, o);
        sq  += __shfl_xor_sync(0xFFFFFFFFu, sq,  o);
    }
    __shared__ float s1[4], s2[4];
    int wid = tid >> 5, lane = tid & 31;
    if (lane == 0) { s1[wid] = sum; s2[wid] = sq; }
    __syncthreads();
    float tot  = s1[0] + s1[1] + s1[2] + s1[3];
    float totq = s2[0] + s2[1] + s2[2] + s2[3];

    float mu  = tot * (1.0f / C);
    float var = totq * (1.0f / C) - mu * mu;
    float rs  = rsqrtf(var + 1e-5f);
    float gm  = gamma[0];

    #pragma unroll
    for (int i = 0; i < 4; i++) {
        int c = tid + i * 128;
        float ln = (y[i] - mu) * rs * w[c] + bb[c];
        out[(size_t)row * C + c] = x[(size_t)row * C + c] + gm * ln;
    }
}

// ---------------- launch ----------------------------------------------------
extern "C" void kernel_launch(void* const* d_in, const int* in_sizes, int n_in,
                              void* d_out, int out_size)
{
    const float* x     = (const float*)d_in[0];
    const float* mask  = (const float*)d_in[1];
    const float* Wq    = (const float*)d_in[2];
    const float* Wk    = (const float*)d_in[3];
    const float* Wv    = (const float*)d_in[4];
    const float* Wp    = (const float*)d_in[5];
    const float* bp    = (const float*)d_in[6];
    const float* lnw   = (const float*)d_in[7];
    const float* lnb   = (const float*)d_in[8];
    const float* gamma = (const float*)d_in[9];
    float* out = (float*)d_out;

    float *qp, *kp, *vp, *op, *pp;
    cudaGetSymbolAddress((void**)&qp, g_q);
    cudaGetSymbolAddress((void**)&kp, g_k);
    cudaGetSymbolAddress((void**)&vp, g_v);
    cudaGetSymbolAddress((void**)&op, g_o);
    cudaGetSymbolAddress((void**)&pp, g_p);

    // 1) Q,K,V projections (batched over z)
    sgemm_nt<<<dim3(C / BN, M_TOT / BM, 3), 256>>>(
        x, Wq, Wk, Wv, qp, kp, vp, M_TOT, C, C);

    // 2) mask compression (independent of GEMMs but same stream is fine)
    build_csr<<<E / 4, 128>>>(mask);

    // 3) per-(b,h) V column sums
    vsum_kernel<<<Bsz * H, 512>>>();

    // 4) sparse masked attention
    attn_sparse<<<(Bsz * H * E) / 8, 256>>>();

    // 5) output projection
    sgemm_nt<<<dim3(C / BN, M_TOT / BM, 1), 256>>>(
        op, Wp, Wp, Wp, pp, pp, pp, M_TOT, C, C);

    // 6) bias + LN + residual
    ln_residual<<<M_TOT, 128>>>(x, bp, lnw, lnb, gamma, out);
}

// round 2
// speedup vs baseline: 1.7776x; 1.7776x over previous
#include <cuda_runtime.h>
#include <cuda_bf16.h>

// Problem constants
#define Bsz 2
#define E 2048
#define C 512
#define H 8
#define D 64
#define M_TOT (Bsz * E)       // 4096
#define CAP 320               // per-row nnz capacity (mean ~102)

// ---------------- scratch (device globals; no allocation) ----------------
__device__ float g_q[M_TOT * C];
__device__ float g_k[M_TOT * C];
__device__ float g_v[M_TOT * C];
__device__ float g_o[M_TOT * C];
__device__ float g_p[M_TOT * C];
__device__ int   g_cnt[E];
__device__ int   g_cidx[E * CAP];
__device__ float g_cval[E * CAP];
__device__ float g_vsum[Bsz * H * D];

// =============== tf32 tensor-core GEMM:  C[m,n] = sum_k A[m,k]*B[n,k] =====
// BM=128, BN=64, BK=32. 256 threads = 8 warps in 4(m) x 2(n); warp tile 32x32.
#define TM 128
#define TN 64
#define TK 32
#define SAP (TM + 8)   // As row stride (floats) -> conflict-free frag loads
#define SBP (TN + 8)

__device__ __forceinline__ unsigned f2tf(float f) {
    unsigned r;
    asm("cvt.rna.tf32.f32 %0, %1;" : "=r"(r) : "f"(f));
    return r;
}

__device__ __forceinline__ void mma_tf32(float* c, const unsigned* a, const unsigned* b) {
    asm volatile(
        "mma.sync.aligned.m16n8k8.row.col.f32.tf32.tf32.f32 "
        "{%0,%1,%2,%3}, {%4,%5,%6,%7}, {%8,%9}, {%0,%1,%2,%3};\n"
        : "+f"(c[0]), "+f"(c[1]), "+f"(c[2]), "+f"(c[3])
        : "r"(a[0]), "r"(a[1]), "r"(a[2]), "r"(a[3]), "r"(b[0]), "r"(b[1]));
}

__global__ __launch_bounds__(256) void gemm_tf32(
    const float* __restrict__ A,
    const float* __restrict__ B0, const float* __restrict__ B1, const float* __restrict__ B2,
    float* __restrict__ C0, float* __restrict__ C1, float* __restrict__ C2,
    int M, int N, int K)
{
    int z = blockIdx.z;
    const float* Bm = (z == 0) ? B0 : (z == 1 ? B1 : B2);
    float*       Cm = (z == 0) ? C0 : (z == 1 ? C1 : C2);

    __shared__ float As[TK][SAP];
    __shared__ float Bs[TK][SBP];

    int tid  = threadIdx.x;
    int lane = tid & 31;
    int warp = tid >> 5;
    int m0 = blockIdx.y * TM;
    int n0 = blockIdx.x * TN;

    // global->smem loader indices
    int ar = tid >> 1;             // 0..127
    int ac = (tid & 1) * 16;       // 0 or 16 (16 consecutive floats)
    int br = tid >> 2;             // 0..63
    int bc = (tid & 3) * 8;        // 0,8,16,24 (8 consecutive floats)

    const float* Ag = A  + (size_t)(m0 + ar) * K + ac;
    const float* Bg = Bm + (size_t)(n0 + br) * K + bc;

    // warp tile
    int m_base = (warp >> 1) * 32;
    int n_base = (warp & 1) * 32;
    int lrow = lane >> 2;          // 0..7
    int lcol = lane & 3;           // 0..3

    float acc[2][4][4];
    #pragma unroll
    for (int mi = 0; mi < 2; mi++)
        #pragma unroll
        for (int ni = 0; ni < 4; ni++)
            #pragma unroll
            for (int r = 0; r < 4; r++) acc[mi][ni][r] = 0.0f;

    const int nk = K / TK;   // 16

    // prefetch tile 0
    float4 pa[4], pb[2];
    #pragma unroll
    for (int j = 0; j < 4; j++) pa[j] = *reinterpret_cast<const float4*>(Ag + 4 * j);
    #pragma unroll
    for (int j = 0; j < 2; j++) pb[j] = *reinterpret_cast<const float4*>(Bg + 4 * j);

    // store tile 0
    #pragma unroll
    for (int j = 0; j < 4; j++) {
        As[ac + 4 * j + 0][ar] = __uint_as_float(f2tf(pa[j].x));
        As[ac + 4 * j + 1][ar] = __uint_as_float(f2tf(pa[j].y));
        As[ac + 4 * j + 2][ar] = __uint_as_float(f2tf(pa[j].z));
        As[ac + 4 * j + 3][ar] = __uint_as_float(f2tf(pa[j].w));
    }
    #pragma unroll
    for (int j = 0; j < 2; j++) {
        Bs[bc + 4 * j + 0][br] = __uint_as_float(f2tf(pb[j].x));
        Bs[bc + 4 * j + 1][br] = __uint_as_float(f2tf(pb[j].y));
        Bs[bc + 4 * j + 2][br] = __uint_as_float(f2tf(pb[j].z));
        Bs[bc + 4 * j + 3][br] = __uint_as_float(f2tf(pb[j].w));
    }
    __syncthreads();

    for (int kt = 0; kt < nk; kt++) {
        bool more = (kt + 1) < nk;
        if (more) {
            const float* Agn = Ag + (kt + 1) * TK;
            const float* Bgn = Bg + (kt + 1) * TK;
            #pragma unroll
            for (int j = 0; j < 4; j++) pa[j] = *reinterpret_cast<const float4*>(Agn + 4 * j);
            #pragma unroll
            for (int j = 0; j < 2; j++) pb[j] = *reinterpret_cast<const float4*>(Bgn + 4 * j);
        }

        #pragma unroll
        for (int ks = 0; ks < 4; ks++) {
            int k0 = ks * 8;
            unsigned afr[2][4];
            #pragma unroll
            for (int mi = 0; mi < 2; mi++) {
                int row = m_base + mi * 16 + lrow;
                int col = k0 + lcol;
                afr[mi][0] = __float_as_uint(As[col][row]);
                afr[mi][1] = __float_as_uint(As[col][row + 8]);
                afr[mi][2] = __float_as_uint(As[col + 4][row]);
                afr[mi][3] = __float_as_uint(As[col + 4][row + 8]);
            }
            unsigned bfr[4][2];
            #pragma unroll
            for (int ni = 0; ni < 4; ni++) {
                int nn2 = n_base + ni * 8 + lrow;
                int col = k0 + lcol;
                bfr[ni][0] = __float_as_uint(Bs[col][nn2]);
                bfr[ni][1] = __float_as_uint(Bs[col + 4][nn2]);
            }
            #pragma unroll
            for (int mi = 0; mi < 2; mi++)
                #pragma unroll
                for (int ni = 0; ni < 4; ni++)
                    mma_tf32(acc[mi][ni], afr[mi], bfr[ni]);
        }

        if (more) {
            __syncthreads();
            #pragma unroll
            for (int j = 0; j < 4; j++) {
                As[ac + 4 * j + 0][ar] = __uint_as_float(f2tf(pa[j].x));
                As[ac + 4 * j + 1][ar] = __uint_as_float(f2tf(pa[j].y));
                As[ac + 4 * j + 2][ar] = __uint_as_float(f2tf(pa[j].z));
                As[ac + 4 * j + 3][ar] = __uint_as_float(f2tf(pa[j].w));
            }
            #pragma unroll
            for (int j = 0; j < 2; j++) {
                Bs[bc + 4 * j + 0][br] = __uint_as_float(f2tf(pb[j].x));
                Bs[bc + 4 * j + 1][br] = __uint_as_float(f2tf(pb[j].y));
                Bs[bc + 4 * j + 2][br] = __uint_as_float(f2tf(pb[j].z));
                Bs[bc + 4 * j + 3][br] = __uint_as_float(f2tf(pb[j].w));
            }
            __syncthreads();
        }
    }

    // epilogue
    #pragma unroll
    for (int mi = 0; mi < 2; mi++) {
        #pragma unroll
        for (int ni = 0; ni < 4; ni++) {
            int r  = m0 + m_base + mi * 16 + lrow;
            int cc = n0 + n_base + ni * 8 + lcol * 2;
            float2 s0 = make_float2(acc[mi][ni][0], acc[mi][ni][1]);
            float2 s1 = make_float2(acc[mi][ni][2], acc[mi][ni][3]);
            *reinterpret_cast<float2*>(Cm + (size_t)r * N + cc)       = s0;
            *reinterpret_cast<float2*>(Cm + (size_t)(r + 8) * N + cc) = s1;
        }
    }
}

// ---------------- mask -> per-row compressed lists ------------------------
__global__ __launch_bounds__(128) void build_csr(const float* __restrict__ mask)
{
    int row  = blockIdx.x * 4 + (threadIdx.x >> 5);
    int lane = threadIdx.x & 31;
    if (row >= E) return;

    int cnt = 0;
    const float* mrow = mask + (size_t)row * E;
    for (int j0 = 0; j0 < E; j0 += 32) {
        float v = mrow[j0 + lane];
        unsigned bal = __ballot_sync(0xFFFFFFFFu, v != 0.0f);
        if (v != 0.0f) {
            int off = cnt + __popc(bal & ((1u << lane) - 1u));
            if (off < CAP) {
                g_cidx[row * CAP + off] = j0 + lane;
                g_cval[row * CAP + off] = v;
            }
        }
        cnt += __popc(bal);
    }
    if (lane == 0) g_cnt[row] = (cnt > CAP) ? CAP : cnt;
}

// ---------------- vsum[b,h,d] = sum_e v[b,e,h*64+d] -----------------------
__global__ __launch_bounds__(512) void vsum_kernel()
{
    int bh = blockIdx.x;           // 0..15
    int b = bh >> 3, h = bh & 7;
    int d  = threadIdx.x & 63;
    int sl = threadIdx.x >> 6;     // 0..7
    const float* vb = g_v + (size_t)b * E * C + h * D + d;
    float s = 0.0f;
    #pragma unroll 4
    for (int e = sl; e < E; e += 8) s += vb[(size_t)e * C];
    __shared__ float red[8][64];
    red[sl][d] = s;
    __syncthreads();
    if (sl == 0) {
        float t = 0.0f;
        #pragma unroll
        for (int i = 0; i < 8; i++) t += red[i][d];
        g_vsum[bh * D + d] = t;
    }
}

// ---------------- sparse masked attention v2 -------------------------------
// warp per (b,h,q); half-warp (16 lanes x float4) per neighbor; 4 nbrs/warp-iter.
__global__ __launch_bounds__(256) void attn_sparse2()
{
    int g    = blockIdx.x * 8 + (threadIdx.x >> 5);   // 0..32767
    int lane = threadIdx.x & 31;
    int half = lane >> 4;        // 0 / 1
    int hl   = lane & 15;        // 0..15
    int b = g >> 14;
    int h = (g >> 11) & 7;
    int q = g & (E - 1);

    size_t rowq = ((size_t)(b * E + q)) * C + h * D;
    float4 qv = *reinterpret_cast<const float4*>(g_q + rowq + hl * 4);

    float4 acc = make_float4(0.f, 0.f, 0.f, 0.f);
    if (half == 0) {
        float4 t = *reinterpret_cast<const float4*>(g_vsum + (b * H + h) * D + hl * 4);
        acc.x = 0.5f * t.x; acc.y = 0.5f * t.y;
        acc.z = 0.5f * t.z; acc.w = 0.5f * t.w;
    }

    int n = g_cnt[q];
    int nn = (n + 3) & ~3;
    const int*   ci = g_cidx + q * CAP;
    const float* cv = g_cval + q * CAP;
    size_t base = (size_t)b * E * C + h * D;

    for (int i0 = half; i0 < nn; i0 += 4) {
        int i1 = i0 + 2;
        bool v0 = i0 < n, v1 = i1 < n;
        int   k0i = v0 ? ci[i0] : 0;
        float mv0 = v0 ? cv[i0] : 0.0f;
        int   k1i = v1 ? ci[i1] : 0;
        float mv1 = v1 ? cv[i1] : 0.0f;

        const float* r0 = g_k + base + (size_t)k0i * C;
        const float* r1 = g_k + base + (size_t)k1i * C;
        float4 kv0 = *reinterpret_cast<const float4*>(r0 + hl * 4);
        float4 kv1 = *reinterpret_cast<const float4*>(r1 + hl * 4);
        // hoist v loads to overlap with the shuffle chains
        const float* w0 = g_v + base + (size_t)k0i * C;
        const float* w1 = g_v + base + (size_t)k1i * C;
        float4 vv0 = *reinterpret_cast<const float4*>(w0 + hl * 4);
        float4 vv1 = *reinterpret_cast<const float4*>(w1 + hl * 4);

        float p0 = qv.x * kv0.x + qv.y * kv0.y + qv.z * kv0.z + qv.w * kv0.w;
        float p1 = qv.x * kv1.x + qv.y * kv1.y + qv.z * kv1.z + qv.w * kv1.w;

        p0 += __shfl_xor_sync(0xFFFFFFFFu, p0, 8);
        p1 += __shfl_xor_sync(0xFFFFFFFFu, p1, 8);
        p0 += __shfl_xor_sync(0xFFFFFFFFu, p0, 4);
        p1 += __shfl_xor_sync(0xFFFFFFFFu, p1, 4);
        p0 += __shfl_xor_sync(0xFFFFFFFFu, p0, 2);
        p1 += __shfl_xor_sync(0xFFFFFFFFu, p1, 2);
        p0 += __shfl_xor_sync(0xFFFFFFFFu, p0, 1);
        p1 += __shfl_xor_sync(0xFFFFFFFFu, p1, 1);

        float s0 = 0.5f * mv0 * p0;
        float s1 = 0.5f * mv1 * p1;

        acc.x += s0 * vv0.x + s1 * vv1.x;
        acc.y += s0 * vv0.y + s1 * vv1.y;
        acc.z += s0 * vv0.z + s1 * vv1.z;
        acc.w += s0 * vv0.w + s1 * vv1.w;
    }

    // combine the two half-warps
    acc.x += __shfl_xor_sync(0xFFFFFFFFu, acc.x, 16);
    acc.y += __shfl_xor_sync(0xFFFFFFFFu, acc.y, 16);
    acc.z += __shfl_xor_sync(0xFFFFFFFFu, acc.z, 16);
    acc.w += __shfl_xor_sync(0xFFFFFFFFu, acc.w, 16);

    if (half == 0)
        *reinterpret_cast<float4*>(g_o + rowq + hl * 4) = acc;
}

// ---------------- bias + LayerNorm + residual ------------------------------
__global__ __launch_bounds__(128) void ln_residual(
    const float* __restrict__ x,  const float* __restrict__ bp,
    const float* __restrict__ w,  const float* __restrict__ bb,
    const float* __restrict__ gamma, float* __restrict__ out)
{
    int row = blockIdx.x;          // 0..4095
    int tid = threadIdx.x;         // 128
    const float* pr = g_p + (size_t)row * C;

    float y[4];
    float sum = 0.0f, sq = 0.0f;
    #pragma unroll
    for (int i = 0; i < 4; i++) {
        int c = tid + i * 128;
        y[i] = pr[c] + bp[c];
        sum += y[i];
        sq  += y[i] * y[i];
    }
    #pragma unroll
    for (int o = 16; o; o >>= 1) {
        sum += __shfl_xor_sync(0xFFFFFFFFu, sum, o);
        sq  += __shfl_xor_sync(0xFFFFFFFFu, sq,  o);
    }
    __shared__ float s1[4], s2[4];
    int wid = tid >> 5, lane = tid & 31;
    if (lane == 0) { s1[wid] = sum; s2[wid] = sq; }
    __syncthreads();
    float tot  = s1[0] + s1[1] + s1[2] + s1[3];
    float totq = s2[0] + s2[1] + s2[2] + s2[3];

    float mu  = tot * (1.0f / C);
    float var = totq * (1.0f / C) - mu * mu;
    float rs  = rsqrtf(var + 1e-5f);
    float gm  = gamma[0];

    #pragma unroll
    for (int i = 0; i < 4; i++) {
        int c = tid + i * 128;
        float ln = (y[i] - mu) * rs * w[c] + bb[c];
        out[(size_t)row * C + c] = x[(size_t)row * C + c] + gm * ln;
    }
}

// ---------------- launch ----------------------------------------------------
extern "C" void kernel_launch(void* const* d_in, const int* in_sizes, int n_in,
                              void* d_out, int out_size)
{
    const float* x     = (const float*)d_in[0];
    const float* mask  = (const float*)d_in[1];
    const float* Wq    = (const float*)d_in[2];
    const float* Wk    = (const float*)d_in[3];
    const float* Wv    = (const float*)d_in[4];
    const float* Wp    = (const float*)d_in[5];
    const float* bp    = (const float*)d_in[6];
    const float* lnw   = (const float*)d_in[7];
    const float* lnb   = (const float*)d_in[8];
    const float* gamma = (const float*)d_in[9];
    float* out = (float*)d_out;

    float *qp, *kp, *vp, *op, *pp;
    cudaGetSymbolAddress((void**)&qp, g_q);
    cudaGetSymbolAddress((void**)&kp, g_k);
    cudaGetSymbolAddress((void**)&vp, g_v);
    cudaGetSymbolAddress((void**)&op, g_o);
    cudaGetSymbolAddress((void**)&pp, g_p);

    // 1) Q,K,V projections (tf32 tensor cores, batched over z)
    gemm_tf32<<<dim3(C / TN, M_TOT / TM, 3), 256>>>(
        x, Wq, Wk, Wv, qp, kp, vp, M_TOT, C, C);

    // 2) mask compression
    build_csr<<<E / 4, 128>>>(mask);

    // 3) per-(b,h) V column sums
    vsum_kernel<<<Bsz * H, 512>>>();

    // 4) sparse masked attention
    attn_sparse2<<<(Bsz * H * E) / 8, 256>>>();

    // 5) output projection
    gemm_tf32<<<dim3(C / TN, M_TOT / TM, 1), 256>>>(
        op, Wp, Wp, Wp, pp, pp, pp, M_TOT, C, C);

    // 6) bias + LN + residual
    ln_residual<<<M_TOT, 128>>>(x, bp, lnw, lnb, gamma, out);
}

// round 3
// speedup vs baseline: 2.0244x; 1.1388x over previous
#include <cuda_runtime.h>
#include <cuda_bf16.h>

// Problem constants
#define Bsz 2
#define E 2048
#define C 512
#define H 8
#define D 64
#define M_TOT (Bsz * E)       // 4096
#define CAP 320               // per-row nnz capacity (mean ~102, 22 sigma margin)
#define QKVC 1536             // fused q|k|v row length

// ---------------- scratch (device globals; no allocation) ----------------
__device__ float g_qkv[M_TOT * QKVC];   // [b*E+e][ q(0:512) | k(512:1024) | v(1024:1536) ]
__device__ float g_o[M_TOT * C];
__device__ float g_p[M_TOT * C];
__device__ int   g_cnt[E];
__device__ int   g_cidx[E * CAP];
__device__ float g_cval[E * CAP];
__device__ float g_vsum[Bsz * C];

// =============== tf32 tensor-core GEMM v2 =================================
// C[m, coloff+n] = sum_k A[m,k]*B[n,k].  128x128x16 tiles, double-buffered,
// 256 threads = 8 warps (2m x 4n), warp tile 64x32, mma m16n8k8 tf32.
#define GM 128
#define GN 128
#define GK 16
#define GSAP 136   // padded k-major row stride -> conflict-free frag loads

__device__ __forceinline__ unsigned f2tf(float f) {
    unsigned r;
    asm("cvt.rna.tf32.f32 %0, %1;" : "=r"(r) : "f"(f));
    return r;
}

__device__ __forceinline__ void mma_tf32(float* c, const unsigned* a, const unsigned* b) {
    asm volatile(
        "mma.sync.aligned.m16n8k8.row.col.f32.tf32.tf32.f32 "
        "{%0,%1,%2,%3}, {%4,%5,%6,%7}, {%8,%9}, {%0,%1,%2,%3};\n"
        : "+f"(c[0]), "+f"(c[1]), "+f"(c[2]), "+f"(c[3])
        : "r"(a[0]), "r"(a[1]), "r"(a[2]), "r"(a[3]), "r"(b[0]), "r"(b[1]));
}

__global__ __launch_bounds__(256) void gemm_tf32_v2(
    const float* __restrict__ A,
    const float* __restrict__ B0, const float* __restrict__ B1, const float* __restrict__ B2,
    float* __restrict__ Cc, int ldc, int coloff_mul, int K)
{
    int z = blockIdx.z;
    const float* Bm = (z == 0) ? B0 : (z == 1 ? B1 : B2);
    int coloff = z * coloff_mul;

    __shared__ float As[2][GK][GSAP];
    __shared__ float Bs[2][GK][GSAP];

    int tid  = threadIdx.x;
    int lane = tid & 31;
    int warp = tid >> 5;
    int m0 = blockIdx.y * GM;
    int n0 = blockIdx.x * GN;

    // loaders: 2 lanes per row, 8 consecutive k-values (2 float4) each
    int lr = tid >> 1;             // 0..127
    int lc = (tid & 1) * 8;        // 0 or 8
    const float* Ag = A  + (size_t)(m0 + lr) * K + lc;
    const float* Bg = Bm + (size_t)(n0 + lr) * K + lc;

    int m_base = (warp >> 2) * 64;
    int n_base = (warp & 3) * 32;
    int lrow = lane >> 2;          // 0..7
    int lcol = lane & 3;           // 0..3

    float acc[4][4][4];
    #pragma unroll
    for (int mi = 0; mi < 4; mi++)
        #pragma unroll
        for (int ni = 0; ni < 4; ni++)
            #pragma unroll
            for (int r = 0; r < 4; r++) acc[mi][ni][r] = 0.0f;

    const int nt = K / GK;   // 32

    float4 pa[2], pb[2];
    pa[0] = *reinterpret_cast<const float4*>(Ag);
    pa[1] = *reinterpret_cast<const float4*>(Ag + 4);
    pb[0] = *reinterpret_cast<const float4*>(Bg);
    pb[1] = *reinterpret_cast<const float4*>(Bg + 4);

    // store tile 0 into buf 0
    #pragma unroll
    for (int j = 0; j < 2; j++) {
        As[0][lc + 4 * j + 0][lr] = __uint_as_float(f2tf(pa[j].x));
        As[0][lc + 4 * j + 1][lr] = __uint_as_float(f2tf(pa[j].y));
        As[0][lc + 4 * j + 2][lr] = __uint_as_float(f2tf(pa[j].z));
        As[0][lc + 4 * j + 3][lr] = __uint_as_float(f2tf(pa[j].w));
        Bs[0][lc + 4 * j + 0][lr] = __uint_as_float(f2tf(pb[j].x));
        Bs[0][lc + 4 * j + 1][lr] = __uint_as_float(f2tf(pb[j].y));
        Bs[0][lc + 4 * j + 2][lr] = __uint_as_float(f2tf(pb[j].z));
        Bs[0][lc + 4 * j + 3][lr] = __uint_as_float(f2tf(pb[j].w));
    }
    __syncthreads();

    for (int kt = 0; kt < nt; kt++) {
        int cur = kt & 1;
        bool more = (kt + 1) < nt;
        if (more) {
            const float* Ap = Ag + (kt + 1) * GK;
            const float* Bp = Bg + (kt + 1) * GK;
            pa[0] = *reinterpret_cast<const float4*>(Ap);
            pa[1] = *reinterpret_cast<const float4*>(Ap + 4);
            pb[0] = *reinterpret_cast<const float4*>(Bp);
            pb[1] = *reinterpret_cast<const float4*>(Bp + 4);
        }

        #pragma unroll
        for (int ks = 0; ks < 2; ks++) {
            int k0 = ks * 8;
            unsigned afr[4][4];
            #pragma unroll
            for (int mi = 0; mi < 4; mi++) {
                int row = m_base + mi * 16 + lrow;
                afr[mi][0] = __float_as_uint(As[cur][k0 + lcol][row]);
                afr[mi][1] = __float_as_uint(As[cur][k0 + lcol][row + 8]);
                afr[mi][2] = __float_as_uint(As[cur][k0 + lcol + 4][row]);
                afr[mi][3] = __float_as_uint(As[cur][k0 + lcol + 4][row + 8]);
            }
            unsigned bfr[4][2];
            #pragma unroll
            for (int ni = 0; ni < 4; ni++) {
                int nn2 = n_base + ni * 8 + lrow;
                bfr[ni][0] = __float_as_uint(Bs[cur][k0 + lcol][nn2]);
                bfr[ni][1] = __float_as_uint(Bs[cur][k0 + lcol + 4][nn2]);
            }
            #pragma unroll
            for (int mi = 0; mi < 4; mi++)
                #pragma unroll
                for (int ni = 0; ni < 4; ni++)
                    mma_tf32(acc[mi][ni], afr[mi], bfr[ni]);
        }

        if (more) {
            int nxt = cur ^ 1;
            #pragma unroll
            for (int j = 0; j < 2; j++) {
                As[nxt][lc + 4 * j + 0][lr] = __uint_as_float(f2tf(pa[j].x));
                As[nxt][lc + 4 * j + 1][lr] = __uint_as_float(f2tf(pa[j].y));
                As[nxt][lc + 4 * j + 2][lr] = __uint_as_float(f2tf(pa[j].z));
                As[nxt][lc + 4 * j + 3][lr] = __uint_as_float(f2tf(pa[j].w));
                Bs[nxt][lc + 4 * j + 0][lr] = __uint_as_float(f2tf(pb[j].x));
                Bs[nxt][lc + 4 * j + 1][lr] = __uint_as_float(f2tf(pb[j].y));
                Bs[nxt][lc + 4 * j + 2][lr] = __uint_as_float(f2tf(pb[j].z));
                Bs[nxt][lc + 4 * j + 3][lr] = __uint_as_float(f2tf(pb[j].w));
            }
            __syncthreads();
        }
    }

    // epilogue
    #pragma unroll
    for (int mi = 0; mi < 4; mi++) {
        #pragma unroll
        for (int ni = 0; ni < 4; ni++) {
            int r  = m0 + m_base + mi * 16 + lrow;
            int cc = coloff + n0 + n_base + ni * 8 + lcol * 2;
            *reinterpret_cast<float2*>(Cc + (size_t)r * ldc + cc) =
                make_float2(acc[mi][ni][0], acc[mi][ni][1]);
            *reinterpret_cast<float2*>(Cc + (size_t)(r + 8) * ldc + cc) =
                make_float2(acc[mi][ni][2], acc[mi][ni][3]);
        }
    }
}

// ---------------- mask -> per-row compressed lists ------------------------
__global__ __launch_bounds__(128) void build_csr(const float* __restrict__ mask)
{
    int row  = blockIdx.x * 4 + (threadIdx.x >> 5);
    int lane = threadIdx.x & 31;
    if (row >= E) return;

    int cnt = 0;
    const float* mrow = mask + (size_t)row * E;
    for (int j0 = 0; j0 < E; j0 += 32) {
        float v = mrow[j0 + lane];
        unsigned bal = __ballot_sync(0xFFFFFFFFu, v != 0.0f);
        if (v != 0.0f) {
            int off = cnt + __popc(bal & ((1u << lane) - 1u));
            if (off < CAP) {
                g_cidx[row * CAP + off] = j0 + lane;
                g_cval[row * CAP + off] = v;
            }
        }
        cnt += __popc(bal);
    }
    if (lane == 0) g_cnt[row] = (cnt > CAP) ? CAP : cnt;
}

// ---------------- vsum[b][h*64+d] = sum_e v[b,e,h,d] ----------------------
__global__ __launch_bounds__(512) void vsum_kernel()
{
    int bh = blockIdx.x;           // 0..15
    int b = bh >> 3, h = bh & 7;
    int d  = threadIdx.x & 63;
    int sl = threadIdx.x >> 6;     // 0..7
    const float* vb = g_qkv + (size_t)b * E * QKVC + 1024 + h * D + d;
    float s = 0.0f;
    #pragma unroll 4
    for (int e = sl; e < E; e += 8) s += vb[(size_t)e * QKVC];
    __shared__ float red[8][64];
    red[sl][d] = s;
    __syncthreads();
    if (sl == 0) {
        float t = 0.0f;
        #pragma unroll
        for (int i = 0; i < 8; i++) t += red[i][d];
        g_vsum[b * C + h * D + d] = t;
    }
}

// ---------------- sparse masked attention v3 -------------------------------
// One block (256 threads) per query q: covers both batches x all 8 heads.
// thread -> (bb = tid>>7, position c = (tid&127)*4); head = c/64.
// Per nnz: contiguous 1KB k|v load, 16-lane dot-reduce, axpy.
__global__ __launch_bounds__(256) void attn_sparse3()
{
    __shared__ int   sc[CAP];
    __shared__ float sv[CAP];

    int q   = blockIdx.x;
    int tid = threadIdx.x;
    int bb  = tid >> 7;           // batch 0/1
    int t   = tid & 127;
    int c   = t * 4;              // 0..508

    int n    = g_cnt[q];
    int npad = (n + 3) & ~3;
    for (int i = tid; i < npad; i += 256) {
        sc[i] = (i < n) ? g_cidx[q * CAP + i] : 0;
        sv[i] = (i < n) ? g_cval[q * CAP + i] : 0.0f;
    }
    __syncthreads();

    size_t qrow = ((size_t)(bb * E + q)) * QKVC;
    float4 qv = *reinterpret_cast<const float4*>(g_qkv + qrow + c);
    float4 vs = *reinterpret_cast<const float4*>(g_vsum + bb * C + c);
    float4 acc = make_float4(0.5f * vs.x, 0.5f * vs.y, 0.5f * vs.z, 0.5f * vs.w);

    const float* kb = g_qkv + (size_t)bb * E * QKVC + 512 + c;  // k row base (+512 -> v)

    for (int i = 0; i < npad; i += 4) {
        int   i0 = sc[i],     i1 = sc[i + 1], i2 = sc[i + 2], i3 = sc[i + 3];
        float m0 = sv[i],     m1 = sv[i + 1], m2 = sv[i + 2], m3 = sv[i + 3];

        const float* r0 = kb + (size_t)i0 * QKVC;
        const float* r1 = kb + (size_t)i1 * QKVC;
        const float* r2 = kb + (size_t)i2 * QKVC;
        const float* r3 = kb + (size_t)i3 * QKVC;

        float4 k0 = *reinterpret_cast<const float4*>(r0);
        float4 k1 = *reinterpret_cast<const float4*>(r1);
        float4 k2 = *reinterpret_cast<const float4*>(r2);
        float4 k3 = *reinterpret_cast<const float4*>(r3);
        float4 v0 = *reinterpret_cast<const float4*>(r0 + 512);
        float4 v1 = *reinterpret_cast<const float4*>(r1 + 512);
        float4 v2 = *reinterpret_cast<const float4*>(r2 + 512);
        float4 v3 = *reinterpret_cast<const float4*>(r3 + 512);

        float p0 = qv.x * k0.x + qv.y * k0.y + qv.z * k0.z + qv.w * k0.w;
        float p1 = qv.x * k1.x + qv.y * k1.y + qv.z * k1.z + qv.w * k1.w;
        float p2 = qv.x * k2.x + qv.y * k2.y + qv.z * k2.z + qv.w * k2.w;
        float p3 = qv.x * k3.x + qv.y * k3.y + qv.z * k3.z + qv.w * k3.w;

        // reduce within each 16-lane head group; all lanes end with the sum
        #pragma unroll
        for (int o = 1; o < 16; o <<= 1) {
            p0 += __shfl_xor_sync(0xFFFFFFFFu, p0, o);
            p1 += __shfl_xor_sync(0xFFFFFFFFu, p1, o);
            p2 += __shfl_xor_sync(0xFFFFFFFFu, p2, o);
            p3 += __shfl_xor_sync(0xFFFFFFFFu, p3, o);
        }

        float s0 = 0.5f * m0 * p0;
        float s1 = 0.5f * m1 * p1;
        float s2 = 0.5f * m2 * p2;
        float s3 = 0.5f * m3 * p3;

        acc.x += s0 * v0.x + s1 * v1.x + s2 * v2.x + s3 * v3.x;
        acc.y += s0 * v0.y + s1 * v1.y + s2 * v2.y + s3 * v3.y;
        acc.z += s0 * v0.z + s1 * v1.z + s2 * v2.z + s3 * v3.z;
        acc.w += s0 * v0.w + s1 * v1.w + s2 * v2.w + s3 * v3.w;
    }

    *reinterpret_cast<float4*>(g_o + ((size_t)(bb * E + q)) * C + c) = acc;
}

// ---------------- bias + LayerNorm + residual ------------------------------
__global__ __launch_bounds__(128) void ln_residual(
    const float* __restrict__ x,  const float* __restrict__ bp,
    const float* __restrict__ w,  const float* __restrict__ bb,
    const float* __restrict__ gamma, float* __restrict__ out)
{
    int row = blockIdx.x;          // 0..4095
    int tid = threadIdx.x;         // 128
    const float* pr = g_p + (size_t)row * C;

    float y[4];
    float sum = 0.0f, sq = 0.0f;
    #pragma unroll
    for (int i = 0; i < 4; i++) {
        int c = tid + i * 128;
        y[i] = pr[c] + bp[c];
        sum += y[i];
        sq  += y[i] * y[i];
    }
    #pragma unroll
    for (int o = 16; o; o >>= 1) {
        sum += __shfl_xor_sync(0xFFFFFFFFu, sum, o);
        sq  += __shfl_xor_sync(0xFFFFFFFFu, sq,  o);
    }
    __shared__ float s1[4], s2[4];
    int wid = tid >> 5, lane = tid & 31;
    if (lane == 0) { s1[wid] = sum; s2[wid] = sq; }
    __syncthreads();
    float tot  = s1[0] + s1[1] + s1[2] + s1[3];
    float totq = s2[0] + s2[1] + s2[2] + s2[3];

    float mu  = tot * (1.0f / C);
    float var = totq * (1.0f / C) - mu * mu;
    float rs  = rsqrtf(var + 1e-5f);
    float gm  = gamma[0];

    #pragma unroll
    for (int i = 0; i < 4; i++) {
        int c = tid + i * 128;
        float ln = (y[i] - mu) * rs * w[c] + bb[c];
        out[(size_t)row * C + c] = x[(size_t)row * C + c] + gm * ln;
    }
}

// ---------------- launch ----------------------------------------------------
extern "C" void kernel_launch(void* const* d_in, const int* in_sizes, int n_in,
                              void* d_out, int out_size)
{
    const float* x     = (const float*)d_in[0];
    const float* mask  = (const float*)d_in[1];
    const float* Wq    = (const float*)d_in[2];
    const float* Wk    = (const float*)d_in[3];
    const float* Wv    = (const float*)d_in[4];
    const float* Wp    = (const float*)d_in[5];
    const float* bp    = (const float*)d_in[6];
    const float* lnw   = (const float*)d_in[7];
    const float* lnb   = (const float*)d_in[8];
    const float* gamma = (const float*)d_in[9];
    float* out = (float*)d_out;

    float *qkvp, *op, *pp;
    cudaGetSymbolAddress((void**)&qkvp, g_qkv);
    cudaGetSymbolAddress((void**)&op, g_o);
    cudaGetSymbolAddress((void**)&pp, g_p);

    // 1) fused QKV projection into g_qkv[M][1536]
    gemm_tf32_v2<<<dim3(C / GN, M_TOT / GM, 3), 256>>>(
        x, Wq, Wk, Wv, qkvp, QKVC, 512, C);

    // 2) mask compression
    build_csr<<<E / 4, 128>>>(mask);

    // 3) per-(b,h) V column sums
    vsum_kernel<<<Bsz * H, 512>>>();

    // 4) sparse masked attention: block per query
    attn_sparse3<<<E, 256>>>();

    // 5) output projection
    gemm_tf32_v2<<<dim3(C / GN, M_TOT / GM, 1), 256>>>(
        op, Wp, Wp, Wp, pp, C, 0, C);

    // 6) bias + LN + residual
    ln_residual<<<M_TOT, 128>>>(x, bp, lnw, lnb, gamma, out);
}